// round 1
// baseline (speedup 1.0000x reference)
#include <cuda_runtime.h>
#include <cstdint>

// ---------------------------------------------------------------------------
// SkipGram negative-sampling: bit-exact JAX threefry gumbel top-k + dot products
// V=100000 vocab, D=512 dim, B=1024 batch, C=20 context, NEG=64 negatives
// ---------------------------------------------------------------------------

#define VV   100000
#define DD   512
#define BB   1024
#define CC   20
#define NEG  64
#define CAP  2048          // candidate buffer per row (mean ~665, ~50 sigma headroom)
#define T0   (-6.5)        // prefilter threshold in score space

// Accurate libdevice logf — identical to what XLA emits for f32 log, and immune
// to -use_fast_math substitution of logf -> __logf.
extern "C" __device__ float __nv_logf(float);

// -------- static scratch (no allocations allowed) --------
__device__ float    d_logp[VV];
__device__ unsigned d_thresh[VV];          // (K_v << 9): keep iff bits >= thresh
__device__ int      d_cnt[BB];
__device__ unsigned d_cand_bits[BB * CAP];
__device__ int      d_cand_v[BB * CAP];
__device__ int      d_negidx[BB * NEG];

// ---------------------------------------------------------------------------
// threefry2x32, key = (0, 42)  ->  ks0=0, ks1=42, ks2 = 0x1BD11BDA ^ 42
// Partitionable JAX path: per-element counter i (hi=0, lo=i), bits = x0 ^ x1.
// ---------------------------------------------------------------------------
#define TFR(r) { x0 += x1; x1 = __funnelshift_l(x1, x1, (r)); x1 ^= x0; }

__device__ __forceinline__ unsigned tf_bits(unsigned ctr) {
    const unsigned ks1 = 42u, ks2 = 0x1BD11BF0u;
    unsigned x0 = 0u;          // ctr_hi(0) + ks0(0)
    unsigned x1 = ctr + ks1;
    TFR(13) TFR(15) TFR(26) TFR(6)
    x0 += ks1; x1 += ks2 + 1u;
    TFR(17) TFR(29) TFR(16) TFR(24)
    x0 += ks2; x1 += 2u;               // ks0 + 2
    TFR(13) TFR(15) TFR(26) TFR(6)
    /* x0 += ks0 */ x1 += ks1 + 3u;
    TFR(17) TFR(29) TFR(16) TFR(24)
    x0 += ks1; x1 += ks2 + 4u;
    TFR(13) TFR(15) TFR(26) TFR(6)
    x0 += ks2; x1 += 5u;               // ks0 + 5
    return x0 ^ x1;
}

// ---------------------------------------------------------------------------
// k0: per-word tables. logp (exact f32, matches XLA) + conservative integer
// prefilter threshold computed in double:
//   keep v iff score could exceed T0  <=>  u > exp(-exp(logp - T0))
// margin 0.02 in score space covers all f32 rounding wobble. Also zeroes cnt.
// ---------------------------------------------------------------------------
__global__ __launch_bounds__(256) void k0_tables(const float* __restrict__ p) {
    int v = blockIdx.x * 256 + threadIdx.x;
    if (v < BB) d_cnt[v] = 0;
    if (v >= VV) return;
    float pf = p[v];
    d_logp[v] = __nv_logf(pf);
    double lp = log((double)pf);
    double E = exp(lp - (T0 - 0.02));
    double ucrit = exp(-E);
    long long m = (long long)(floor(ucrit * 8388608.0)) - 2;
    if (m < 0) m = 0;
    if (m > 8388607) m = 8388607;
    d_thresh[v] = ((unsigned)m) << 9;
}

// ---------------------------------------------------------------------------
// k1: hot loop. One threefry + one integer compare per (b, v). Survivors are
// pushed with warp-aggregated atomics. Each thread owns 4 consecutive v
// (uint4 threshold load), grid.y = b.
// ---------------------------------------------------------------------------
__global__ __launch_bounds__(256) void k1_filter() {
    const int b  = blockIdx.y;
    const int tg = blockIdx.x * 256 + threadIdx.x;
    const int v0 = tg * 4;
    const bool valid = (v0 < VV);      // VV % 4 == 0, so all 4 valid together

    uint4 th = make_uint4(0xFFFFFFFFu, 0xFFFFFFFFu, 0xFFFFFFFFu, 0xFFFFFFFFu);
    if (valid) th = *(const uint4*)&d_thresh[v0];

    unsigned base = (unsigned)b * (unsigned)VV + (unsigned)v0;

    unsigned bits[4]; bool kp[4];
#pragma unroll
    for (int j = 0; j < 4; j++) { bits[j] = 0u; kp[j] = false; }
    if (valid) {
        bits[0] = tf_bits(base + 0u);
        bits[1] = tf_bits(base + 1u);
        bits[2] = tf_bits(base + 2u);
        bits[3] = tf_bits(base + 3u);
        kp[0] = bits[0] >= th.x;
        kp[1] = bits[1] >= th.y;
        kp[2] = bits[2] >= th.z;
        kp[3] = bits[3] >= th.w;
    }
    int nk = (int)kp[0] + (int)kp[1] + (int)kp[2] + (int)kp[3];

    // warp inclusive scan -> exclusive offset + warp total
    const unsigned fm = 0xFFFFFFFFu;
    const int lane = threadIdx.x & 31;
    int inc = nk;
#pragma unroll
    for (int d2 = 1; d2 < 32; d2 <<= 1) {
        int t = __shfl_up_sync(fm, inc, d2);
        if (lane >= d2) inc += t;
    }
    int excl  = inc - nk;
    int total = __shfl_sync(fm, inc, 31);
    int wbase = 0;
    if (lane == 31 && total > 0) wbase = atomicAdd(&d_cnt[b], total);
    wbase = __shfl_sync(fm, wbase, 31);

    int slot = wbase + excl;
#pragma unroll
    for (int j = 0; j < 4; j++) {
        if (kp[j] && slot < CAP) {
            d_cand_bits[b * CAP + slot] = bits[j];
            d_cand_v[b * CAP + slot]    = v0 + j;
            slot++;
        }
    }
}

// ---------------------------------------------------------------------------
// k2: per-row exact rescoring (reference f32 arithmetic) + bitonic top-64.
// key = (ordered(score) << 32) | (0xFFFFFFFF - v): ascending sort, read from
// the end => score desc, index asc (matches XLA top_k tie-break).
// ---------------------------------------------------------------------------
__global__ __launch_bounds__(256) void k2_select() {
    __shared__ unsigned long long key[CAP];
    const int b = blockIdx.x;
    int n = d_cnt[b];
    if (n > CAP) n = CAP;

    for (int s = threadIdx.x; s < CAP; s += 256) {
        unsigned long long kk = 0ull;
        if (s < n) {
            unsigned bits = d_cand_bits[b * CAP + s];
            int v = d_cand_v[b * CAP + s];
            unsigned m = bits >> 9;
            // uniform in [tiny, 1): exact JAX arithmetic
            float f  = __fadd_rn(__uint_as_float(m | 0x3f800000u), -1.0f);
            float u  = __fadd_rn(f, 1.17549435e-38f);
            float e  = -__nv_logf(u);
            float g  = -__nv_logf(e);
            float sc = __fadd_rn(d_logp[v], g);
            unsigned sb = __float_as_uint(sc);
            sb = (sb & 0x80000000u) ? ~sb : (sb | 0x80000000u);
            kk = ((unsigned long long)sb << 32)
               | (unsigned long long)(0xFFFFFFFFu - (unsigned)v);
        }
        key[s] = kk;
    }
    __syncthreads();

    int sz = 64;
    while (sz < n) sz <<= 1;   // <= CAP

    for (int kk2 = 2; kk2 <= sz; kk2 <<= 1) {
        for (int j = kk2 >> 1; j > 0; j >>= 1) {
            for (int i = threadIdx.x; i < sz; i += 256) {
                int l = i ^ j;
                if (l > i) {
                    unsigned long long a = key[i], c = key[l];
                    bool up = ((i & kk2) == 0);
                    if ((a > c) == up) { key[i] = c; key[l] = a; }
                }
            }
            __syncthreads();
        }
    }

    if (threadIdx.x < NEG) {
        unsigned long long kk = key[sz - 1 - threadIdx.x];
        unsigned v = 0xFFFFFFFFu - (unsigned)(kk & 0xFFFFFFFFull);
        if (v >= VV) v = 0;   // unreachable in practice; OOB guard
        d_negidx[b * NEG + threadIdx.x] = (int)v;
    }
}

// ---------------------------------------------------------------------------
// k3: gathers + dot products. One CTA per b; center embedding cached in smem;
// one warp per output (20 positives from W_center [faithful quirk], 64
// negatives from W_context).
// ---------------------------------------------------------------------------
__global__ __launch_bounds__(256) void k3_dots(const int* __restrict__ center_ids,
                                               const int* __restrict__ context_ids,
                                               const float* __restrict__ Wc,
                                               const float* __restrict__ Wx,
                                               float* __restrict__ out) {
    __shared__ float ctr[DD];
    const int b = blockIdx.x;
    const size_t crow = (size_t)center_ids[b] * DD;
    for (int i = threadIdx.x; i < DD; i += 256) ctr[i] = Wc[crow + i];
    __syncthreads();

    const int warp = threadIdx.x >> 5;
    const int lane = threadIdx.x & 31;
    const float4* ctr4 = (const float4*)ctr;

    for (int j = warp; j < CC + NEG; j += 8) {
        const float* row;
        if (j < CC) row = Wc + (size_t)context_ids[b * CC + j] * DD;
        else        row = Wx + (size_t)d_negidx[b * NEG + (j - CC)] * DD;
        const float4* row4 = (const float4*)row;
        float acc = 0.0f;
#pragma unroll
        for (int t = 0; t < 4; t++) {
            float4 r = row4[lane + 32 * t];
            float4 c = ctr4[lane + 32 * t];
            acc += r.x * c.x + r.y * c.y + r.z * c.z + r.w * c.w;
        }
#pragma unroll
        for (int d2 = 16; d2 > 0; d2 >>= 1)
            acc += __shfl_down_sync(0xFFFFFFFFu, acc, d2);
        if (lane == 0) {
            if (j < CC) out[b * CC + j] = acc;
            else        out[BB * CC + b * NEG + (j - CC)] = acc;
        }
    }
}

// ---------------------------------------------------------------------------
extern "C" void kernel_launch(void* const* d_in, const int* in_sizes, int n_in,
                              void* d_out, int out_size) {
    const int*   center_ids  = (const int*)d_in[0];
    const int*   context_ids = (const int*)d_in[1];
    const float* W_center    = (const float*)d_in[2];
    const float* W_context   = (const float*)d_in[3];
    const float* sample_prob = (const float*)d_in[4];
    float* out = (float*)d_out;

    k0_tables<<<(VV + 255) / 256, 256>>>(sample_prob);

    dim3 g1((VV / 4 + 255) / 256, BB);   // 98 x 1024 CTAs
    k1_filter<<<g1, 256>>>();

    k2_select<<<BB, 256>>>();

    k3_dots<<<BB, 256>>>(center_ids, context_ids, W_center, W_context, out);
}

// round 2
// speedup vs baseline: 1.1951x; 1.1951x over previous
#include <cuda_runtime.h>
#include <cstdint>

// ---------------------------------------------------------------------------
// SkipGram negative-sampling: bit-exact JAX threefry gumbel top-k + dot products
// V=100000, D=512, B=1024, C=20, NEG=64
// ---------------------------------------------------------------------------

#define VV   100000
#define DD   512
#define BB   1024
#define CC   20
#define NEG  64
#define CAP  2048
#define T0   (-5.5)        // prefilter threshold: mean survivors e^5.5 ~ 245/row

extern "C" __device__ float __nv_logf(float);

// -------- static scratch --------
__device__ float    d_logp[VV];
__device__ unsigned d_thresh[VV];
__device__ int      d_cnt[BB];
__device__ unsigned d_cand_bits[BB * CAP];
__device__ int      d_cand_v[BB * CAP];
__device__ int      d_negidx[BB * NEG];

// ---------------------------------------------------------------------------
// threefry2x32, key (0,42). Round add forced to IMAD via opaque `one` so the
// alu pipe only carries SHF+LOP3 (2 ops/round) and the fma pipe carries IMAD.
// ---------------------------------------------------------------------------
#define TFR(r) { x0 = x0 * one + x1; x1 = __funnelshift_l(x1, x1, (r)); x1 ^= x0; }

__device__ __forceinline__ unsigned tf_bits(unsigned ctr, unsigned one) {
    const unsigned ks1 = 42u, ks2 = 0x1BD11BF0u;
    unsigned x0 = 0u;
    unsigned x1 = ctr + ks1;
    TFR(13) TFR(15) TFR(26) TFR(6)
    x0 += ks1; x1 += ks2 + 1u;
    TFR(17) TFR(29) TFR(16) TFR(24)
    x0 += ks2; x1 += 2u;
    TFR(13) TFR(15) TFR(26) TFR(6)
    x1 += ks1 + 3u;
    TFR(17) TFR(29) TFR(16) TFR(24)
    x0 += ks1; x1 += ks2 + 4u;
    TFR(13) TFR(15) TFR(26) TFR(6)
    x0 += ks2; x1 += 5u;
    return x0 ^ x1;
}

// ---------------------------------------------------------------------------
// k0: per-word logp (exact f32) + conservative integer prefilter threshold
// (computed in double, margin 0.02 in score space). Zeroes cnt.
// ---------------------------------------------------------------------------
__global__ __launch_bounds__(256) void k0_tables(const float* __restrict__ p) {
    int v = blockIdx.x * 256 + threadIdx.x;
    if (v < BB) d_cnt[v] = 0;
    if (v >= VV) return;
    float pf = p[v];
    d_logp[v] = __nv_logf(pf);
    double lp = log((double)pf);
    double E = exp(lp - (T0 - 0.02));
    double ucrit = exp(-E);
    long long m = (long long)(floor(ucrit * 8388608.0)) - 2;
    if (m < 0) m = 0;
    if (m > 8388607) m = 8388607;
    d_thresh[v] = ((unsigned)m) << 9;
}

// ---------------------------------------------------------------------------
// k1: hot loop. 8 consecutive v per thread (two uint4 threshold loads),
// one threefry + one unsigned compare each. Warp-aggregated push.
// ---------------------------------------------------------------------------
__global__ __launch_bounds__(256) void k1_filter(unsigned one) {
    const int b  = blockIdx.y;
    const int tg = blockIdx.x * 256 + threadIdx.x;
    const int v0 = tg * 8;
    const bool valid = (v0 < VV);          // VV % 8 == 0

    uint4 thA = make_uint4(~0u, ~0u, ~0u, ~0u);
    uint4 thB = thA;
    if (valid) {
        thA = *(const uint4*)&d_thresh[v0];
        thB = *(const uint4*)&d_thresh[v0 + 4];
    }
    unsigned th[8] = {thA.x, thA.y, thA.z, thA.w, thB.x, thB.y, thB.z, thB.w};

    unsigned base = (unsigned)b * (unsigned)VV + (unsigned)v0;

    unsigned bits[8]; bool kp[8];
    int nk = 0;
#pragma unroll
    for (int j = 0; j < 8; j++) {
        bits[j] = valid ? tf_bits(base + (unsigned)j, one) : 0u;
        kp[j]   = valid && (bits[j] >= th[j]);
        nk += (int)kp[j];
    }

    const unsigned fm = 0xFFFFFFFFu;
    const int lane = threadIdx.x & 31;
    int inc = nk;
#pragma unroll
    for (int d2 = 1; d2 < 32; d2 <<= 1) {
        int t = __shfl_up_sync(fm, inc, d2);
        if (lane >= d2) inc += t;
    }
    int excl  = inc - nk;
    int total = __shfl_sync(fm, inc, 31);
    int wbase = 0;
    if (lane == 31 && total > 0) wbase = atomicAdd(&d_cnt[b], total);
    wbase = __shfl_sync(fm, wbase, 31);

    int slot = wbase + excl;
#pragma unroll
    for (int j = 0; j < 8; j++) {
        if (kp[j] && slot < CAP) {
            d_cand_bits[b * CAP + slot] = bits[j];
            d_cand_v[b * CAP + slot]    = v0 + j;
            slot++;
        }
    }
}

// ---------------------------------------------------------------------------
// k2: exact rescoring (reference f32 arithmetic) + bitonic top-64.
// key = ordered(score)<<32 | (~v): ascending sort; read from end gives
// score desc, index asc (XLA tie-break).
// ---------------------------------------------------------------------------
__global__ __launch_bounds__(256) void k2_select() {
    __shared__ unsigned long long key[CAP];
    const int b = blockIdx.x;
    int n = d_cnt[b];
    if (n > CAP) n = CAP;

    for (int s = threadIdx.x; s < CAP; s += 256) {
        unsigned long long kk = 0ull;
        if (s < n) {
            unsigned bits = d_cand_bits[b * CAP + s];
            int v = d_cand_v[b * CAP + s];
            unsigned m = bits >> 9;
            float f  = __fadd_rn(__uint_as_float(m | 0x3f800000u), -1.0f);
            float u  = __fadd_rn(f, 1.17549435e-38f);
            float e  = -__nv_logf(u);
            float g  = -__nv_logf(e);
            float sc = __fadd_rn(d_logp[v], g);
            unsigned sb = __float_as_uint(sc);
            sb = (sb & 0x80000000u) ? ~sb : (sb | 0x80000000u);
            kk = ((unsigned long long)sb << 32)
               | (unsigned long long)(0xFFFFFFFFu - (unsigned)v);
        }
        key[s] = kk;
    }
    __syncthreads();

    int sz = 64;
    while (sz < n) sz <<= 1;

    for (int kk2 = 2; kk2 <= sz; kk2 <<= 1) {
        for (int j = kk2 >> 1; j > 0; j >>= 1) {
            for (int i = threadIdx.x; i < sz; i += 256) {
                int l = i ^ j;
                if (l > i) {
                    unsigned long long a = key[i], c = key[l];
                    bool up = ((i & kk2) == 0);
                    if ((a > c) == up) { key[i] = c; key[l] = a; }
                }
            }
            __syncthreads();
        }
    }

    if (threadIdx.x < NEG) {
        unsigned long long kk = key[sz - 1 - threadIdx.x];
        unsigned v = 0xFFFFFFFFu - (unsigned)(kk & 0xFFFFFFFFull);
        if (v >= VV) v = 0;
        d_negidx[b * NEG + threadIdx.x] = (int)v;
    }
}

// ---------------------------------------------------------------------------
// k3: gathers + dots. grid (B, 2): each CTA handles 42 of the 84 outputs for
// its row -> 2x in-flight rows for latency hiding. Center cached in smem.
// ---------------------------------------------------------------------------
__global__ __launch_bounds__(256) void k3_dots(const int* __restrict__ center_ids,
                                               const int* __restrict__ context_ids,
                                               const float* __restrict__ Wc,
                                               const float* __restrict__ Wx,
                                               float* __restrict__ out) {
    __shared__ float ctr[DD];
    const int b = blockIdx.x;
    const size_t crow = (size_t)center_ids[b] * DD;
    for (int i = threadIdx.x; i < DD; i += 256) ctr[i] = Wc[crow + i];
    __syncthreads();

    const int warp = threadIdx.x >> 5;
    const int lane = threadIdx.x & 31;
    const float4* ctr4 = (const float4*)ctr;

    const int j0 = blockIdx.y * 42;
    const int j1 = (blockIdx.y == 0) ? 42 : (CC + NEG);

    for (int j = j0 + warp; j < j1; j += 8) {
        const float* row;
        if (j < CC) row = Wc + (size_t)context_ids[b * CC + j] * DD;
        else        row = Wx + (size_t)d_negidx[b * NEG + (j - CC)] * DD;
        const float4* row4 = (const float4*)row;
        float acc = 0.0f;
#pragma unroll
        for (int t = 0; t < 4; t++) {
            float4 r = row4[lane + 32 * t];
            float4 c = ctr4[lane + 32 * t];
            acc += r.x * c.x + r.y * c.y + r.z * c.z + r.w * c.w;
        }
#pragma unroll
        for (int d2 = 16; d2 > 0; d2 >>= 1)
            acc += __shfl_down_sync(0xFFFFFFFFu, acc, d2);
        if (lane == 0) {
            if (j < CC) out[b * CC + j] = acc;
            else        out[BB * CC + b * NEG + (j - CC)] = acc;
        }
    }
}

// ---------------------------------------------------------------------------
extern "C" void kernel_launch(void* const* d_in, const int* in_sizes, int n_in,
                              void* d_out, int out_size) {
    const int*   center_ids  = (const int*)d_in[0];
    const int*   context_ids = (const int*)d_in[1];
    const float* W_center    = (const float*)d_in[2];
    const float* W_context   = (const float*)d_in[3];
    const float* sample_prob = (const float*)d_in[4];
    float* out = (float*)d_out;

    k0_tables<<<(VV + 255) / 256, 256>>>(sample_prob);

    dim3 g1((VV / 8 + 255) / 256, BB);   // 49 x 1024 CTAs
    k1_filter<<<g1, 256>>>(1u);

    k2_select<<<BB, 256>>>();

    dim3 g3(BB, 2);
    k3_dots<<<g3, 256>>>(center_ids, context_ids, W_center, W_context, out);
}